// round 9
// baseline (speedup 1.0000x reference)
#include <cuda_runtime.h>
#include <cuda.h>

#define NS      32768
#define NT      512
#define SEASK   24
#define LEVW    512
#define SEAW    536
#define LOGW    511

#define NWARP   32          // series per block (= compute lanes)
#define BLOCK   64          // warp 0: compute, warp 1: IO
#define NPER    21
#define RSTRIDE 28          // y smem row stride: conflict-free .128
#define LPACK   24          // packed tile rows for TMA
#define Y0S     12

__device__ __forceinline__ unsigned smem_u32(const void* p) {
    return (unsigned)__cvta_generic_to_shared(p);
}
__device__ __forceinline__ void cp16(unsigned dst, const void* src) {
    asm volatile("cp.async.cg.shared.global [%0], [%1], 16;\n" :: "r"(dst), "l"(src) : "memory");
}
__device__ __forceinline__ void cp_commit() {
    asm volatile("cp.async.commit_group;\n" ::: "memory");
}
template<int N> __device__ __forceinline__ void cp_wait() {
    asm volatile("cp.async.wait_group %0;\n" :: "n"(N) : "memory");
}
__device__ __forceinline__ void tma_store2d(const void* map, int x, int y, unsigned smem) {
    asm volatile("cp.async.bulk.tensor.2d.global.shared::cta.tile.bulk_group [%0, {%1, %2}], [%3];"
                 :: "l"(map), "r"(x), "r"(y), "r"(smem) : "memory");
}
__device__ __forceinline__ void bulk_commit() {
    asm volatile("cp.async.bulk.commit_group;" ::: "memory");
}
template<int N> __device__ __forceinline__ void bulk_wait() {
    asm volatile("cp.async.bulk.wait_group %0;" :: "n"(N) : "memory");
}
__device__ __forceinline__ void fence_async_shared() {
    asm volatile("fence.proxy.async.shared::cta;" ::: "memory");
}

// 12-step sub-batch, P0 compile-time. Slots (P0+k)%24 distinct within the
// period -> each read sees the value from exactly 24 steps ago (matches ref).
template<int P0>
__device__ __forceinline__ void half12(
    const float* __restrict__ ysm, float* __restrict__ lb, float* __restrict__ sb,
    float* __restrict__ db,
    float a, float oma, float& lev, float& llev, float (&sbuf)[SEASK])
{
    float q_[12], nl_[12];
    #pragma unroll
    for (int k = 0; k < 12; k++) {
        const int pp = (P0 + k) % SEASK;
        const float sv = sbuf[pp];
        q_[k]    = a * __fdividef(ysm[k], sv);
        sbuf[pp] = oma * sv;                        // fold (1-a)*seas in place
    }
    #pragma unroll
    for (int k = 0; k < 12; k++) { nl_[k] = fmaf(oma, lev, q_[k]); lev = nl_[k]; }
    #pragma unroll
    for (int k = 0; k < 12; k++) {
        const int pp = (P0 + k) % SEASK;
        sbuf[pp] = fmaf(a, __fdividef(ysm[k], nl_[k]), sbuf[pp]);
    }
    #pragma unroll
    for (int m = 0; m < 3; m++) {
        *(float4*)(lb + 4*m) = make_float4(nl_[4*m], nl_[4*m+1], nl_[4*m+2], nl_[4*m+3]);
        *(float4*)(sb + 4*m) = make_float4(sbuf[(P0+4*m)   % SEASK], sbuf[(P0+4*m+1) % SEASK],
                                           sbuf[(P0+4*m+2) % SEASK], sbuf[(P0+4*m+3) % SEASK]);
        float d0, d1, d2, d3, ll;
        ll = __logf(nl_[4*m+0]); d0 = ll - llev; llev = ll;
        ll = __logf(nl_[4*m+1]); d1 = ll - llev; llev = ll;
        ll = __logf(nl_[4*m+2]); d2 = ll - llev; llev = ll;
        ll = __logf(nl_[4*m+3]); d3 = ll - llev; llev = ll;
        *(float4*)(db + 4*m) = make_float4(d0, d1, d2, d3);
    }
}

__global__ __launch_bounds__(BLOCK, 7) void es_fwd_kernel(
    const __grid_constant__ CUtensorMap tml,
    const __grid_constant__ CUtensorMap tms,
    const float* __restrict__ y,
    const int*   __restrict__ idxs,
    const float* __restrict__ lev_sms_p,
    const float* __restrict__ init_seas_p,
    float* __restrict__ out)
{
    __shared__ __align__(16) float ybuf[3][NWARP * RSTRIDE];
    __shared__ __align__(16) float y0buf[NWARP * Y0S];
    __shared__ __align__(16) float ltile[2][NWARP * LPACK];
    __shared__ __align__(16) float stile[2][NWARP * LPACK];
    __shared__ __align__(16) float dtile[2][NWARP * LPACK];

    const int tid  = threadIdx.x;
    const int wid  = tid >> 5;
    const int lane = tid & 31;
    const int s0   = blockIdx.x * NWARP;

    float* gl = out;
    float* gs = out + (size_t)NS * LEVW;
    float* gd = gs  + (size_t)NS * SEAW;

    if (wid == 0) {
        // ===================== COMPUTE WARP =====================
        const int s   = s0 + lane;
        const int idx = idxs[s];
        // reference derives BOTH smoothing params from lev_sms (its own quirk)
        const float a   = 1.0f / (1.0f + __expf(-lev_sms_p[idx]));
        const float oma = 1.0f - a;

        const char* ybase = (const char*)(y + (size_t)s0 * NT);
        const unsigned ysb[3] = { smem_u32(ybuf[0]), smem_u32(ybuf[1]), smem_u32(ybuf[2]) };

        // async y loads: G0 = steps 0..7, G1/G2 = periods 0,1
        #pragma unroll
        for (int j = 0; j < 2; j++) {
            const int f = lane + 32 * j;
            const int row = f >> 1, col = f & 1;
            cp16(smem_u32(y0buf) + row * (Y0S * 4) + col * 16,
                 ybase + row * (NT * 4) + col * 16);
        }
        cp_commit();
        #pragma unroll
        for (int p = 0; p < 2; p++) {
            #pragma unroll
            for (int j = 0; j < 6; j++) {
                const int f = lane + 32 * j;
                const int row = f / 6, col = f % 6;
                cp16(ysb[p] + row * (RSTRIDE * 4) + col * 16,
                     ybase + 32 + 96 * p + row * (NT * 4) + col * 16);
            }
            cp_commit();
        }

        // seasonal state in registers; emit seas cols 0..23
        float sbuf[SEASK];
        {
            const float4* isr = (const float4*)(init_seas_p + (size_t)idx * SEASK);
            float4* gsr = (float4*)(gs + (size_t)s * SEAW);
            #pragma unroll
            for (int qd = 0; qd < 6; qd++) {
                float4 v = isr[qd];
                v.x = __expf(v.x); v.y = __expf(v.y); v.z = __expf(v.z); v.w = __expf(v.w);
                sbuf[4*qd+0] = v.x; sbuf[4*qd+1] = v.y;
                sbuf[4*qd+2] = v.z; sbuf[4*qd+3] = v.w;
                __stcs(gsr + qd, v);
            }
        }

        float lev, llev;

        // ---- peel steps 0..7 (direct stores; tiny) ----
        cp_wait<2>();
        __syncwarp();
        {
            const float4 v0 = *(const float4*)(y0buf + lane * Y0S);
            const float4 v1 = *(const float4*)(y0buf + lane * Y0S + 4);
            float yt[8] = {v0.x, v0.y, v0.z, v0.w, v1.x, v1.y, v1.z, v1.w};
            float q_[8], nl_[8], dt_[8];

            const float st0 = sbuf[0];
            lev  = __fdividef(yt[0], st0);
            llev = __logf(lev);
            nl_[0] = lev; dt_[0] = 0.0f;

            #pragma unroll
            for (int k = 1; k < 8; k++) {
                const float sv = sbuf[k];
                q_[k]   = a * __fdividef(yt[k], sv);
                sbuf[k] = oma * sv;
            }
            #pragma unroll
            for (int k = 1; k < 8; k++) { nl_[k] = fmaf(oma, lev, q_[k]); lev = nl_[k]; }
            #pragma unroll
            for (int k = 1; k < 8; k++)
                sbuf[k] = fmaf(a, __fdividef(yt[k], nl_[k]), sbuf[k]);
            #pragma unroll
            for (int k = 1; k < 8; k++) {
                const float ll = __logf(nl_[k]);
                dt_[k] = ll - llev; llev = ll;
            }

            float* lb = ltile[0] + lane * 8;     // temp staging (8-wide packed)
            float* sb = stile[0] + lane * 8;
            float* db = dtile[0] + lane * 8;
            *(float4*)(lb)     = make_float4(nl_[0], nl_[1], nl_[2], nl_[3]);
            *(float4*)(lb + 4) = make_float4(nl_[4], nl_[5], nl_[6], nl_[7]);
            *(float4*)(sb)     = make_float4(st0, sbuf[1], sbuf[2], sbuf[3]);
            *(float4*)(sb + 4) = make_float4(sbuf[4], sbuf[5], sbuf[6], sbuf[7]);
            *(float4*)(db)     = make_float4(dt_[0], dt_[1], dt_[2], dt_[3]);
            *(float4*)(db + 4) = make_float4(dt_[4], dt_[5], dt_[6], dt_[7]);
            __syncwarp();

            #pragma unroll
            for (int j = 0; j < 2; j++) {
                const int f = lane + 32 * j;
                const int row = f >> 1, qd = f & 1;
                __stcs((float4*)(gl + (size_t)(s0 + row) * LEVW) + qd,
                       ((const float4*)(ltile[0] + row * 8))[qd]);
                __stcs((float4*)(gs + (size_t)(s0 + row) * SEAW + SEASK) + qd,
                       ((const float4*)(stile[0] + row * 8))[qd]);
            }
            // gd: plain stores (keep in L2 so later adjacent writes merge sectors)
            #pragma unroll
            for (int j = 0; j < 7; j++) {
                const int i = lane + 32 * j;
                const int row = i / 7, k = i % 7;
                gd[(size_t)(s0 + row) * LOGW + k] = dtile[0][row * 8 + 1 + k];
            }
            __syncwarp();
        }

        // ---- 21 steady periods ----
        #pragma unroll 1
        for (int p = 0; p < NPER; p++) {
            if (p + 2 < NPER) {
                const char* yb = ybase + 32 + (size_t)(p + 2) * 96;
                const unsigned d = ysb[(p + 2) % 3];
                #pragma unroll
                for (int j = 0; j < 6; j++) {
                    const int f = lane + 32 * j;
                    const int row = f / 6, col = f % 6;
                    cp16(d + row * (RSTRIDE * 4) + col * 16, yb + row * (NT * 4) + col * 16);
                }
                cp_commit();
                cp_wait<2>();
            } else {
                cp_wait<0>();
            }
            __syncwarp();

            const float* ysm = ybuf[p % 3] + lane * RSTRIDE;
            float* lb = ltile[p & 1] + lane * LPACK;
            float* sb = stile[p & 1] + lane * LPACK;
            float* db = dtile[p & 1] + lane * LPACK;

            half12< 8>(ysm,      lb,      sb,      db,      a, oma, lev, llev, sbuf);
            half12<20>(ysm + 12, lb + 12, sb + 12, db + 12, a, oma, lev, llev, sbuf);

            __syncthreads();   // B_p: tiles[p&1] ready; IO has guaranteed group p-2 done
        }
    } else {
        // ===================== IO WARP =====================
        #pragma unroll 1
        for (int p = 0; p < NPER; p++) {
            __syncthreads();   // wait B_p
            const int b  = p & 1;
            const int tp = 8 + 24 * p;

            if (lane == 0) {
                fence_async_shared();
                tma_store2d(&tml, tp,         s0, smem_u32(ltile[b]));
                tma_store2d(&tms, tp + SEASK, s0, smem_u32(stile[b]));
                bulk_commit();
            }

            // log_diff: coalesced scalar PLAIN stores (L2 merges the misaligned
            // boundary sectors with the adjacent period's write; __stcs would
            // evict the partial line first and force DRAM read-modify-write)
            const float* df = dtile[b];
            #pragma unroll
            for (int j = 0; j < 24; j++) {
                const int i = lane + 32 * j;
                const int row = i / 24, k = i % 24;
                gd[(size_t)(s0 + row) * LOGW + tp - 1 + k] = df[i];
            }

            // allow 1 group in flight: groups <= p-1 complete => buffer (p)&1
            // is free for compute's period p+2 overwrite (which happens after B_{p+1})
            if (lane == 0) bulk_wait<1>();
        }
        if (lane == 0) bulk_wait<0>();   // smem must stay alive until TMA drains
    }
}

extern "C" void kernel_launch(void* const* d_in, const int* in_sizes, int n_in,
                              void* d_out, int out_size)
{
    const float* y         = (const float*)d_in[0];
    const int*   idxs      = (const int*)  d_in[1];
    const float* lev_sms   = (const float*)d_in[2];
    const float* init_seas = (const float*)d_in[4];  // d_in[3] unused (reference quirk)
    float* out = (float*)d_out;

    typedef CUresult (*EncodeFn)(CUtensorMap*, CUtensorMapDataType, cuuint32_t, void*,
                                 const cuuint64_t*, const cuuint64_t*, const cuuint32_t*,
                                 const cuuint32_t*, CUtensorMapInterleave, CUtensorMapSwizzle,
                                 CUtensorMapL2promotion, CUtensorMapFloatOOBfill);
    EncodeFn enc = nullptr;
    cudaDriverEntryPointQueryResult qr;
    cudaGetDriverEntryPointByVersion("cuTensorMapEncodeTiled", (void**)&enc, 12000,
                                     cudaEnableDefault, &qr);

    CUtensorMap tml, tms;
    {
        cuuint64_t dims[2]    = { (cuuint64_t)LEVW, (cuuint64_t)NS };
        cuuint64_t strides[1] = { (cuuint64_t)LEVW * 4 };
        cuuint32_t box[2]     = { 24, 32 };
        cuuint32_t es[2]      = { 1, 1 };
        enc(&tml, CU_TENSOR_MAP_DATA_TYPE_FLOAT32, 2, out, dims, strides, box, es,
            CU_TENSOR_MAP_INTERLEAVE_NONE, CU_TENSOR_MAP_SWIZZLE_NONE,
            CU_TENSOR_MAP_L2_PROMOTION_L2_128B, CU_TENSOR_MAP_FLOAT_OOB_FILL_NONE);
    }
    {
        float* gsp = out + (size_t)NS * LEVW;
        cuuint64_t dims[2]    = { (cuuint64_t)SEAW, (cuuint64_t)NS };
        cuuint64_t strides[1] = { (cuuint64_t)SEAW * 4 };
        cuuint32_t box[2]     = { 24, 32 };
        cuuint32_t es[2]      = { 1, 1 };
        enc(&tms, CU_TENSOR_MAP_DATA_TYPE_FLOAT32, 2, gsp, dims, strides, box, es,
            CU_TENSOR_MAP_INTERLEAVE_NONE, CU_TENSOR_MAP_SWIZZLE_NONE,
            CU_TENSOR_MAP_L2_PROMOTION_L2_128B, CU_TENSOR_MAP_FLOAT_OOB_FILL_NONE);
    }

    es_fwd_kernel<<<NS / NWARP, BLOCK>>>(tml, tms, y, idxs, lev_sms, init_seas, out);
}